// round 6
// baseline (speedup 1.0000x reference)
#include <cuda_runtime.h>
#include <cstdint>

#define RESP 32
#define RESF 64
#define NP   8192
#define NF   65536
#define CH   128
#define EPSV 1e-5f

// ---- scratch (device globals: allocation-free rule) ----
__device__ int   g_pg[RESP*RESP*RESP];
__device__ float g_h1[NP*CH];
__device__ float g_out1[NF*CH];
__device__ float g_h2[NF*CH];
__device__ float g_M1s[64*CH*CH];   // aggregated conv1 weights, [mat][n][k], tf32-rounded
__device__ float g_W2s[27*CH*CH];   // conv2 weights, [mat][n][k], tf32-rounded
__device__ float g_sum[32], g_sq[32];      // GN1 stats
__device__ float g_sum2[32], g_sq2[32];    // GN2 stats (accumulated by conv1 epilogue)
__device__ float g_ps[32][32], g_pq[32][32];

// ================= helpers =================
__device__ __forceinline__ uint32_t smem_u32(const void* p) {
    uint32_t a;
    asm("{ .reg .u64 t; cvta.to.shared.u64 t, %1; cvt.u32.u64 %0, t; }" : "=r"(a) : "l"(p));
    return a;
}
__device__ __forceinline__ float tf32r(float x) {
    uint32_t u;
    asm("cvt.rna.tf32.f32 %0, %1;" : "=r"(u) : "f"(x));
    return __uint_as_float(u);
}
__device__ __forceinline__ void cp16(uint32_t dst, const void* src, uint32_t ssz) {
    asm volatile("cp.async.cg.shared.global [%0], [%1], 16, %2;" :: "r"(dst), "l"(src), "r"(ssz));
}
__device__ __forceinline__ void cp_commit() { asm volatile("cp.async.commit_group;"); }
#define CP_WAIT(n) asm volatile("cp.async.wait_group %0;" :: "n"(n) : "memory")

__device__ __forceinline__ void ldsm4(uint32_t* r, uint32_t addr) {
    asm volatile("ldmatrix.sync.aligned.m8n8.x4.shared.b16 {%0,%1,%2,%3}, [%4];"
        : "=r"(r[0]), "=r"(r[1]), "=r"(r[2]), "=r"(r[3]) : "r"(addr));
}
__device__ __forceinline__ void mma_tf32(float* d, const uint32_t* a, const uint32_t* b) {
    asm volatile("mma.sync.aligned.m16n8k8.row.col.f32.tf32.tf32.f32 "
        "{%0,%1,%2,%3}, {%4,%5,%6,%7}, {%8,%9}, {%0,%1,%2,%3};"
        : "+f"(d[0]), "+f"(d[1]), "+f"(d[2]), "+f"(d[3])
        : "r"(a[0]), "r"(a[1]), "r"(a[2]), "r"(a[3]), "r"(b[0]), "r"(b[1]));
}

// ================= grid build + stat zeroing =================
__global__ void k_init_pg() {
    int i = blockIdx.x * blockDim.x + threadIdx.x;
    if (i < RESP*RESP*RESP) g_pg[i] = -1;
    if (blockIdx.x == 0 && threadIdx.x < 32) {
        g_sum2[threadIdx.x] = 0.f; g_sq2[threadIdx.x] = 0.f;
    }
}
__global__ void k_scatter(const int* __restrict__ coords) {
    int i = blockIdx.x * blockDim.x + threadIdx.x;
    if (i < NP) g_pg[(coords[i*3]*RESP + coords[i*3+1])*RESP + coords[i*3+2]] = i;
}

// ================= group norm (GN1 two-phase) =================
__global__ void k_stats1(const float* __restrict__ x, int nrows, int nsl) {
    int g = blockIdx.x, sl = blockIdx.y;
    int per = nrows / nsl, r0 = sl * per;
    float s = 0.f, q = 0.f;
    for (int r = r0 + threadIdx.x; r < r0 + per; r += blockDim.x) {
        float4 v = *reinterpret_cast<const float4*>(x + r*CH + g*4);
        s += (v.x + v.y) + (v.z + v.w);
        q += (v.x*v.x + v.y*v.y) + (v.z*v.z + v.w*v.w);
    }
    __shared__ float ss[256], sq[256];
    ss[threadIdx.x] = s; sq[threadIdx.x] = q;
    __syncthreads();
    for (int st = 128; st > 0; st >>= 1) {
        if (threadIdx.x < st) { ss[threadIdx.x] += ss[threadIdx.x+st]; sq[threadIdx.x] += sq[threadIdx.x+st]; }
        __syncthreads();
    }
    if (threadIdx.x == 0) { g_ps[g][sl] = ss[0]; g_pq[g][sl] = sq[0]; }
}
__global__ void k_stats2(int nsl) {
    int g = blockIdx.x, t = threadIdx.x;
    float s = (t < nsl) ? g_ps[g][t] : 0.f;
    float q = (t < nsl) ? g_pq[g][t] : 0.f;
#pragma unroll
    for (int o = 16; o > 0; o >>= 1) {
        s += __shfl_xor_sync(0xffffffff, s, o);
        q += __shfl_xor_sync(0xffffffff, q, o);
    }
    if (t == 0) { g_sum[g] = s; g_sq[g] = q; }
}
template<bool SECOND>
__global__ void k_gnsilu(const float* __restrict__ xin,
                         const float* __restrict__ gamma, const float* __restrict__ beta,
                         float invcnt, int n4) {
    int idx = blockIdx.x * blockDim.x + threadIdx.x;
    if (idx >= n4) return;
    const float* x = SECOND ? g_out1 : xin;
    float* outp    = SECOND ? g_h2   : g_h1;
    int g = idx & 31;
    float sum = SECOND ? g_sum2[g] : g_sum[g];
    float sq  = SECOND ? g_sq2[g]  : g_sq[g];
    float mean = sum * invcnt;
    float var  = sq * invcnt - mean * mean;
    float inv  = rsqrtf(var + EPSV);
    float4 v  = reinterpret_cast<const float4*>(x)[idx];
    float4 ga = reinterpret_cast<const float4*>(gamma)[g];
    float4 be = reinterpret_cast<const float4*>(beta)[g];
    float4 o; float y;
    y = (v.x - mean)*inv*ga.x + be.x; o.x = tf32r(y / (1.f + expf(-y)));
    y = (v.y - mean)*inv*ga.y + be.y; o.y = tf32r(y / (1.f + expf(-y)));
    y = (v.z - mean)*inv*ga.z + be.z; o.z = tf32r(y / (1.f + expf(-y)));
    y = (v.w - mean)*inv*ga.w + be.w; o.w = tf32r(y / (1.f + expf(-y)));
    reinterpret_cast<float4*>(outp)[idx] = o;
}

// ================= weight preprocessing: transpose to [mat][n][k] + tf32 round =================
__global__ void k_buildM1s(const float* __restrict__ W1) {
    int idx = blockIdx.x * blockDim.x + threadIdx.x;
    if (idx >= 64*CH*CH) return;
    int m = idx >> 14, rest = idx & 16383;
    int n = rest >> 7, kk = rest & 127;
    int k = m >> 3, j = m & 7;
    int s[3], cnt[3];
#pragma unroll
    for (int a = 0; a < 3; a++) {
        int o  = (k >> (2 - a)) & 1;
        int eb = (j >> (2 - a)) & 1;
        cnt[a] = 1 + (o ^ eb);
        s[a]   = -1 + eb * (1 + o);
    }
    float acc = 0.f;
    for (int d0 = 0; d0 < cnt[0]; d0++)
        for (int d1 = 0; d1 < cnt[1]; d1++)
            for (int d2 = 0; d2 < cnt[2]; d2++) {
                int k27 = ((s[0]+d0+1)*3 + (s[1]+d1+1))*3 + (s[2]+d2+1);
                acc += W1[k27*CH*CH + kk*CH + n];
            }
    g_M1s[idx] = tf32r(acc);
}
__global__ void k_buildW2s(const float* __restrict__ W2) {
    int idx = blockIdx.x * blockDim.x + threadIdx.x;
    if (idx >= 27*CH*CH) return;
    int m = idx >> 14, rest = idx & 16383;
    int n = rest >> 7, kk = rest & 127;
    g_W2s[idx] = tf32r(W2[m*CH*CH + kk*CH + n]);
}

// ================= tf32 mma conv kernels =================
// CTA 128x128, 4 warps (2m x 2n), warp tile 64x64.
// BK=32 stages, XOR-swizzled 128B-pitch smem, 3-stage cp.async pipeline.
#define STG_SZ 32768         // A 16KB + B 16KB per stage

template<int NTAPS, bool ISC2>
__global__ __launch_bounds__(128, 2)
void k_convmma(const int* __restrict__ coords, const float* __restrict__ bias,
               const float* __restrict__ feats, float* __restrict__ dout) {
    extern __shared__ char dsm[];
    uint32_t smS = smem_u32(dsm);
    int* snb = (int*)(dsm + 3*STG_SZ);

    const float* hsrc = ISC2 ? g_h2  : g_h1;
    const float* Wp   = ISC2 ? g_W2s : g_M1s;
    float* outp       = ISC2 ? dout  : g_out1;

    int tid = threadIdx.x, lane = tid & 31, wid = tid >> 5;
    int wm = wid >> 1, wn = wid & 1;
    int bx = blockIdx.x, ko = blockIdx.y;
    const int matBase = ISC2 ? 0 : ko*8;

    // ---- neighbor precompute ----
    for (int t = tid; t < NTAPS*128; t += 128) {
        int tap = t >> 7, row = t & 127;
        int nb = -1;
        if (ISC2) {
            int grow = bx*128 + row;
            int pi = grow >> 3, k8 = grow & 7;
            int f0 = 2*coords[pi*3+0] + ((k8 >> 2) & 1) + (tap/9 - 1);
            int f1 = 2*coords[pi*3+1] + ((k8 >> 1) & 1) + ((tap/3) % 3 - 1);
            int f2 = 2*coords[pi*3+2] + (k8 & 1)        + (tap % 3 - 1);
            if ((unsigned)f0 < RESF && (unsigned)f1 < RESF && (unsigned)f2 < RESF) {
                int p = g_pg[((f0 >> 1)*RESP + (f1 >> 1))*RESP + (f2 >> 1)];
                if (p >= 0) nb = p*8 + (((f0 & 1) << 2) | ((f1 & 1) << 1) | (f2 & 1));
            }
        } else {
            int p = bx*128 + row;
            int q0 = coords[p*3+0] + ((ko >> 2) & 1) - 1 + ((tap >> 2) & 1);
            int q1 = coords[p*3+1] + ((ko >> 1) & 1) - 1 + ((tap >> 1) & 1);
            int q2 = coords[p*3+2] + (ko & 1)        - 1 + (tap & 1);
            if ((unsigned)q0 < RESP && (unsigned)q1 < RESP && (unsigned)q2 < RESP)
                nb = g_pg[(q0*RESP + q1)*RESP + q2];
        }
        snb[t] = nb;
    }
    __syncthreads();

    // per-lane ldmatrix constants
    const int laneAr = (lane & 7) + ((lane >> 3) & 1)*8;
    const int laneAc = (lane >> 4) & 1;
    const int laneBr = (lane & 7) + ((lane >> 4) & 1)*8;
    const int laneBc = (lane >> 3) & 1;
    uint32_t offA[4], offB[4]; int rxA[4], rxB[4];
#pragma unroll
    for (int i = 0; i < 4; i++) {
        int rA = wm*64 + i*16 + laneAr;
        offA[i] = (uint32_t)rA * 128u; rxA[i] = rA & 7;
        int rB = wn*64 + i*16 + laneBr;
        offB[i] = 16384u + (uint32_t)rB * 128u; rxB[i] = rB & 7;
    }

    float acc[4][8][4];
#pragma unroll
    for (int mt = 0; mt < 4; mt++)
#pragma unroll
        for (int nt = 0; nt < 8; nt++)
#pragma unroll
            for (int c = 0; c < 4; c++) acc[mt][nt][c] = 0.f;

    const int T = NTAPS * 4;
    const int trx = tid & 7;

#define LOAD_STAGE(S, BUF) do { \
        int tap_ = (S) >> 2, c0_ = ((S) & 3) * 32; \
        int src_ = snb[tap_*128 + tid]; \
        uint32_t ssz_ = src_ >= 0 ? 16u : 0u; \
        const float* ap_ = hsrc + (src_ < 0 ? 0 : src_)*CH + c0_; \
        uint32_t ad_ = smS + (BUF)*STG_SZ + (uint32_t)tid*128u; \
        const float* bp_ = Wp + ((matBase + tap_)*128 + tid)*128 + c0_; \
        uint32_t bd_ = ad_ + 16384u; \
        _Pragma("unroll") \
        for (int c_ = 0; c_ < 8; c_++) { \
            uint32_t sw_ = (uint32_t)((c_ ^ trx) << 4); \
            cp16(ad_ + sw_, ap_ + c_*4, ssz_); \
            cp16(bd_ + sw_, bp_ + c_*4, 16u); \
        } \
        cp_commit(); \
    } while (0)

    LOAD_STAGE(0, 0);
    LOAD_STAGE(1, 1);

    int sbuf = 0;
    for (int s = 0; s < T; s++) {
        if (s + 2 < T) CP_WAIT(1); else CP_WAIT(0);
        __syncthreads();
        if (s + 2 < T) {
            int buf2 = sbuf + 2; if (buf2 >= 3) buf2 -= 3;
            LOAD_STAGE(s + 2, buf2);
        }
        uint32_t stg = smS + (uint32_t)sbuf*STG_SZ;
#pragma unroll
        for (int ks = 0; ks < 4; ks++) {
            int cA = ks*2 + laneAc, cB = ks*2 + laneBc;
            uint32_t a[4][4], b[4][4];
#pragma unroll
            for (int mt = 0; mt < 4; mt++)
                ldsm4(a[mt], stg + offA[mt] + (uint32_t)((cA ^ rxA[mt]) << 4));
#pragma unroll
            for (int p = 0; p < 4; p++)
                ldsm4(b[p], stg + offB[p] + (uint32_t)((cB ^ rxB[p]) << 4));
#pragma unroll
            for (int mt = 0; mt < 4; mt++)
#pragma unroll
                for (int p = 0; p < 4; p++) {
                    mma_tf32(acc[mt][p*2 + 0], a[mt], &b[p][0]);
                    mma_tf32(acc[mt][p*2 + 1], a[mt], &b[p][2]);
                }
        }
        sbuf++; if (sbuf == 3) sbuf = 0;
    }
#undef LOAD_STAGE

    // ---- epilogue ----
    float* sred = (float*)dsm;      // reuse stage smem for GN2 stat reduction
    if (!ISC2) {
        __syncthreads();
        if (tid < 64) sred[tid] = 0.f;
        __syncthreads();
    }

    // per-nt group partials: group(nt) = wn*16 + nt*2 + ((lane&3)>>1)
    float gs[8], gq[8];
#pragma unroll
    for (int nt = 0; nt < 8; nt++) { gs[nt] = 0.f; gq[nt] = 0.f; }

#pragma unroll
    for (int mt = 0; mt < 4; mt++) {
        int rl = wm*64 + mt*16 + (lane >> 2);
#pragma unroll
        for (int half = 0; half < 2; half++) {
            int row = rl + half*8;
            int orow, prow;
            if (ISC2) { orow = bx*128 + row; prow = orow >> 3; }
            else      { orow = (bx*128 + row)*8 + ko; prow = -1; }
#pragma unroll
            for (int nt = 0; nt < 8; nt++) {
                int col = wn*64 + nt*8 + (lane & 3)*2;
                float2 bb = *reinterpret_cast<const float2*>(bias + col);
                float ax = acc[mt][nt][half*2 + 0] + bb.x;
                float ay = acc[mt][nt][half*2 + 1] + bb.y;
                if (ISC2) {
                    float2 rr = *reinterpret_cast<const float2*>(feats + prow*CH + col);
                    ax += rr.x; ay += rr.y;
                } else {
                    gs[nt] += ax + ay;
                    gq[nt] += ax*ax + ay*ay;
                }
                float2 o; o.x = ax; o.y = ay;
                *reinterpret_cast<float2*>(outp + orow*CH + col) = o;
            }
        }
    }

    if (!ISC2) {
#pragma unroll
        for (int nt = 0; nt < 8; nt++) {
            int g = wn*16 + nt*2 + ((lane & 3) >> 1);
            atomicAdd(&sred[g], gs[nt]);
            atomicAdd(&sred[32 + g], gq[nt]);
        }
        __syncthreads();
        if (tid < 32) {
            atomicAdd(&g_sum2[tid], sred[tid]);
            atomicAdd(&g_sq2[tid], sred[32 + tid]);
        }
    }
}

// ================= launch =================
extern "C" void kernel_launch(void* const* d_in, const int* in_sizes, int n_in,
                              void* d_out, int out_size) {
    const float* feats  = (const float*)d_in[0];
    const float* gamma1 = (const float*)d_in[1];
    const float* beta1  = (const float*)d_in[2];
    const float* W1     = (const float*)d_in[3];
    const float* b1     = (const float*)d_in[4];
    const float* gamma2 = (const float*)d_in[5];
    const float* beta2  = (const float*)d_in[6];
    const float* W2     = (const float*)d_in[7];
    const float* b2     = (const float*)d_in[8];
    const int*   coords = (const int*)d_in[9];
    float* out = (float*)d_out;

    const int smem1 = 3*STG_SZ + 8*128*4;    // 102400
    const int smem2 = 3*STG_SZ + 27*128*4;   // 112128
    cudaFuncSetAttribute(k_convmma<8,false>, cudaFuncAttributeMaxDynamicSharedMemorySize, smem1);
    cudaFuncSetAttribute(k_convmma<27,true>, cudaFuncAttributeMaxDynamicSharedMemorySize, smem2);

    k_init_pg<<<128, 256>>>();
    k_scatter<<<32, 256>>>(coords);
    k_buildM1s<<<4096, 256>>>(W1);
    k_buildW2s<<<1728, 256>>>(W2);

    // GN1 + SiLU -> g_h1 (tf32-rounded)
    k_stats1<<<dim3(32, 8), 256>>>(feats, NP, 8);
    k_stats2<<<32, 32>>>(8);
    k_gnsilu<false><<<(NP*32 + 255)/256, 256>>>(feats, gamma1, beta1, 1.f/(NP*4), NP*32);

    // conv1 (parent-level, aggregated taps) -> g_out1, accumulates GN2 stats
    k_convmma<8,false><<<dim3(NP/128, 8), 128, smem1>>>(coords, b1, nullptr, nullptr);

    // GN2 + SiLU -> g_h2 (stats already in g_sum2/g_sq2)
    k_gnsilu<true><<<(NF*32 + 255)/256, 256>>>(nullptr, gamma2, beta2, 1.f/(NF*4), NF*32);

    // conv2 (fine-level, 27 taps) + bias + residual -> out
    k_convmma<27,true><<<NF/128, 128, smem2>>>(coords, b2, feats, out);
}

// round 7
// speedup vs baseline: 1.2238x; 1.2238x over previous
#include <cuda_runtime.h>
#include <cstdint>

#define RESP 32
#define RESF 64
#define NP   8192
#define NF   65536
#define CH   128
#define EPSV 1e-5f

// ---- scratch (device globals: allocation-free rule) ----
__device__ int   g_pg[RESP*RESP*RESP];
__device__ float g_h1[NP*CH];
__device__ float g_out1[NF*CH];
__device__ float g_h2[NF*CH];
__device__ float g_M1s[64*CH*CH];   // aggregated conv1 weights, [mat][n][k], tf32-rounded
__device__ float g_W2s[27*CH*CH];   // conv2 weights, [mat][n][k], tf32-rounded
__device__ float g_sum[32], g_sq[32];      // GN1 stats
__device__ float g_sum2[32], g_sq2[32];    // GN2 stats (accumulated by conv1 epilogue)
__device__ float g_ps[32][32], g_pq[32][32];

// ================= helpers =================
__device__ __forceinline__ uint32_t smem_u32(const void* p) {
    uint32_t a;
    asm("{ .reg .u64 t; cvta.to.shared.u64 t, %1; cvt.u32.u64 %0, t; }" : "=r"(a) : "l"(p));
    return a;
}
__device__ __forceinline__ float tf32r(float x) {
    uint32_t u;
    asm("cvt.rna.tf32.f32 %0, %1;" : "=r"(u) : "f"(x));
    return __uint_as_float(u);
}
__device__ __forceinline__ void cp16(uint32_t dst, const void* src, uint32_t ssz) {
    asm volatile("cp.async.cg.shared.global [%0], [%1], 16, %2;" :: "r"(dst), "l"(src), "r"(ssz));
}
__device__ __forceinline__ void cp_commit() { asm volatile("cp.async.commit_group;"); }
#define CP_WAIT(n) asm volatile("cp.async.wait_group %0;" :: "n"(n) : "memory")

__device__ __forceinline__ void ldsm4(uint32_t* r, uint32_t addr) {
    asm volatile("ldmatrix.sync.aligned.m8n8.x4.shared.b16 {%0,%1,%2,%3}, [%4];"
        : "=r"(r[0]), "=r"(r[1]), "=r"(r[2]), "=r"(r[3]) : "r"(addr));
}
__device__ __forceinline__ void mma_tf32(float* d, const uint32_t* a, const uint32_t* b) {
    asm volatile("mma.sync.aligned.m16n8k8.row.col.f32.tf32.tf32.f32 "
        "{%0,%1,%2,%3}, {%4,%5,%6,%7}, {%8,%9}, {%0,%1,%2,%3};"
        : "+f"(d[0]), "+f"(d[1]), "+f"(d[2]), "+f"(d[3])
        : "r"(a[0]), "r"(a[1]), "r"(a[2]), "r"(a[3]), "r"(b[0]), "r"(b[1]));
}

// ================= grid build + stat zeroing =================
__global__ void k_init_pg() {
    int i = blockIdx.x * blockDim.x + threadIdx.x;
    if (i < RESP*RESP*RESP) g_pg[i] = -1;
    if (blockIdx.x == 0 && threadIdx.x < 32) {
        g_sum2[threadIdx.x] = 0.f; g_sq2[threadIdx.x] = 0.f;
    }
}
__global__ void k_scatter(const int* __restrict__ coords) {
    int i = blockIdx.x * blockDim.x + threadIdx.x;
    if (i < NP) g_pg[(coords[i*3]*RESP + coords[i*3+1])*RESP + coords[i*3+2]] = i;
}

// ================= group norm (GN1 two-phase) =================
__global__ void k_stats1(const float* __restrict__ x, int nrows, int nsl) {
    int g = blockIdx.x, sl = blockIdx.y;
    int per = nrows / nsl, r0 = sl * per;
    float s = 0.f, q = 0.f;
    for (int r = r0 + threadIdx.x; r < r0 + per; r += blockDim.x) {
        float4 v = *reinterpret_cast<const float4*>(x + r*CH + g*4);
        s += (v.x + v.y) + (v.z + v.w);
        q += (v.x*v.x + v.y*v.y) + (v.z*v.z + v.w*v.w);
    }
    __shared__ float ss[256], sq[256];
    ss[threadIdx.x] = s; sq[threadIdx.x] = q;
    __syncthreads();
    for (int st = 128; st > 0; st >>= 1) {
        if (threadIdx.x < st) { ss[threadIdx.x] += ss[threadIdx.x+st]; sq[threadIdx.x] += sq[threadIdx.x+st]; }
        __syncthreads();
    }
    if (threadIdx.x == 0) { g_ps[g][sl] = ss[0]; g_pq[g][sl] = sq[0]; }
}
__global__ void k_stats2(int nsl) {
    int g = blockIdx.x, t = threadIdx.x;
    float s = (t < nsl) ? g_ps[g][t] : 0.f;
    float q = (t < nsl) ? g_pq[g][t] : 0.f;
#pragma unroll
    for (int o = 16; o > 0; o >>= 1) {
        s += __shfl_xor_sync(0xffffffff, s, o);
        q += __shfl_xor_sync(0xffffffff, q, o);
    }
    if (t == 0) { g_sum[g] = s; g_sq[g] = q; }
}
template<bool SECOND>
__global__ void k_gnsilu(const float* __restrict__ xin,
                         const float* __restrict__ gamma, const float* __restrict__ beta,
                         float invcnt, int n4) {
    int idx = blockIdx.x * blockDim.x + threadIdx.x;
    if (idx >= n4) return;
    const float* x = SECOND ? g_out1 : xin;
    float* outp    = SECOND ? g_h2   : g_h1;
    int g = idx & 31;
    float sum = SECOND ? g_sum2[g] : g_sum[g];
    float sq  = SECOND ? g_sq2[g]  : g_sq[g];
    float mean = sum * invcnt;
    float var  = sq * invcnt - mean * mean;
    float inv  = rsqrtf(var + EPSV);
    float4 v  = reinterpret_cast<const float4*>(x)[idx];
    float4 ga = reinterpret_cast<const float4*>(gamma)[g];
    float4 be = reinterpret_cast<const float4*>(beta)[g];
    float4 o; float y;
    y = (v.x - mean)*inv*ga.x + be.x; o.x = tf32r(y / (1.f + expf(-y)));
    y = (v.y - mean)*inv*ga.y + be.y; o.y = tf32r(y / (1.f + expf(-y)));
    y = (v.z - mean)*inv*ga.z + be.z; o.z = tf32r(y / (1.f + expf(-y)));
    y = (v.w - mean)*inv*ga.w + be.w; o.w = tf32r(y / (1.f + expf(-y)));
    reinterpret_cast<float4*>(outp)[idx] = o;
}

// ================= weight preprocessing: transpose to [mat][n][k] + tf32 round =================
__global__ void k_buildM1s(const float* __restrict__ W1) {
    int idx = blockIdx.x * blockDim.x + threadIdx.x;
    if (idx >= 64*CH*CH) return;
    int m = idx >> 14, rest = idx & 16383;
    int n = rest >> 7, kk = rest & 127;
    int k = m >> 3, j = m & 7;
    int s[3], cnt[3];
#pragma unroll
    for (int a = 0; a < 3; a++) {
        int o  = (k >> (2 - a)) & 1;
        int eb = (j >> (2 - a)) & 1;
        cnt[a] = 1 + (o ^ eb);
        s[a]   = -1 + eb * (1 + o);
    }
    float acc = 0.f;
    for (int d0 = 0; d0 < cnt[0]; d0++)
        for (int d1 = 0; d1 < cnt[1]; d1++)
            for (int d2 = 0; d2 < cnt[2]; d2++) {
                int k27 = ((s[0]+d0+1)*3 + (s[1]+d1+1))*3 + (s[2]+d2+1);
                acc += W1[k27*CH*CH + kk*CH + n];
            }
    g_M1s[idx] = tf32r(acc);
}
__global__ void k_buildW2s(const float* __restrict__ W2) {
    int idx = blockIdx.x * blockDim.x + threadIdx.x;
    if (idx >= 27*CH*CH) return;
    int m = idx >> 14, rest = idx & 16383;
    int n = rest >> 7, kk = rest & 127;
    g_W2s[idx] = tf32r(W2[m*CH*CH + kk*CH + n]);
}

// ================= tf32 mma conv kernels =================
// CTA: 128 rows x 128 cols, 8 warps (4m x 2n), warp tile 32x64.
// 3-stage cp.async pipeline, BK=16, row pitch 20 floats (conflict-free ldmatrix).
#define STG_PITCH 10240          // 128 rows * 80 B
#define ROW_P 80

template<int NTAPS, bool ISC2>
__global__ __launch_bounds__(256)
void k_convmma(const int* __restrict__ coords, const float* __restrict__ bias,
               const float* __restrict__ feats, float* __restrict__ dout) {
    extern __shared__ char dsm[];
    uint32_t smA = smem_u32(dsm);              // 3 * 10240
    uint32_t smB = smA + 3*STG_PITCH;          // 3 * 10240
    int* snb = (int*)(dsm + 6*STG_PITCH);      // NTAPS*128 ints

    const float* hsrc = ISC2 ? g_h2  : g_h1;
    const float* Wp   = ISC2 ? g_W2s : g_M1s;
    float* outp       = ISC2 ? dout  : g_out1;

    int tid = threadIdx.x, lane = tid & 31, wid = tid >> 5;
    int wm = wid & 3, wn = wid >> 2;
    int bx = blockIdx.x, ko = blockIdx.y;
    const int matBase = ISC2 ? 0 : ko*8;

    // ---- neighbor precompute ----
    for (int t = tid; t < NTAPS*128; t += 256) {
        int tap = t >> 7, row = t & 127;
        int nb = -1;
        if (ISC2) {
            int grow = bx*128 + row;
            int pi = grow >> 3, k8 = grow & 7;
            int f0 = 2*coords[pi*3+0] + ((k8 >> 2) & 1) + (tap/9 - 1);
            int f1 = 2*coords[pi*3+1] + ((k8 >> 1) & 1) + ((tap/3) % 3 - 1);
            int f2 = 2*coords[pi*3+2] + (k8 & 1)        + (tap % 3 - 1);
            if ((unsigned)f0 < RESF && (unsigned)f1 < RESF && (unsigned)f2 < RESF) {
                int p = g_pg[((f0 >> 1)*RESP + (f1 >> 1))*RESP + (f2 >> 1)];
                if (p >= 0) nb = p*8 + (((f0 & 1) << 2) | ((f1 & 1) << 1) | (f2 & 1));
            }
        } else {
            int p = bx*128 + row;
            int q0 = coords[p*3+0] + ((ko >> 2) & 1) - 1 + ((tap >> 2) & 1);
            int q1 = coords[p*3+1] + ((ko >> 1) & 1) - 1 + ((tap >> 1) & 1);
            int q2 = coords[p*3+2] + (ko & 1)        - 1 + (tap & 1);
            if ((unsigned)q0 < RESP && (unsigned)q1 < RESP && (unsigned)q2 < RESP)
                nb = g_pg[(q0*RESP + q1)*RESP + q2];
        }
        snb[t] = nb;
    }
    __syncthreads();

    // per-thread loader coords: 2 cp16 for A row, 2 for B row
    const int lrow = tid >> 1, lhalf = tid & 1;

    // per-thread ldmatrix bases (stage-0 absolute; add stage offset later)
    uint32_t Abase = smA + (uint32_t)((wm*32 + ((lane>>3)&1)*8 + (lane&7))*ROW_P + ((lane>>4)&1)*16);
    uint32_t Bbase = smB + (uint32_t)((wn*64 + ((lane>>4)&1)*8 + (lane&7))*ROW_P + ((lane>>3)&1)*16);

    float acc[2][8][4];
#pragma unroll
    for (int mt = 0; mt < 2; mt++)
#pragma unroll
        for (int nt = 0; nt < 8; nt++)
#pragma unroll
            for (int c = 0; c < 4; c++) acc[mt][nt][c] = 0.f;

    const int T = NTAPS * 8;

    // prologue: stages 0,1
#pragma unroll
    for (int s = 0; s < 2; s++) {
        int tap = s >> 3, c0 = (s & 7) * 16;
        int src = snb[tap*128 + lrow];
        uint32_t ssz = src >= 0 ? 16u : 0u;
        const float* ap = hsrc + (src < 0 ? 0 : src)*CH + c0 + lhalf*8;
        uint32_t ad = smA + s*STG_PITCH + lrow*ROW_P + lhalf*32;
        cp16(ad, ap, ssz); cp16(ad + 16, ap + 4, ssz);
        const float* bp = Wp + ((matBase + tap)*128 + lrow)*128 + c0 + lhalf*8;
        uint32_t bd = smB + s*STG_PITCH + lrow*ROW_P + lhalf*32;
        cp16(bd, bp, 16u); cp16(bd + 16, bp + 4, 16u);
        cp_commit();
    }

    int sbuf = 0;
    for (int s = 0; s < T; s++) {
        if (s + 2 < T) CP_WAIT(1); else CP_WAIT(0);
        __syncthreads();
        if (s + 2 < T) {
            int s2 = s + 2;
            int tap = s2 >> 3, c0 = (s2 & 7) * 16;
            int buf2 = sbuf + 2; if (buf2 >= 3) buf2 -= 3;
            int src = snb[tap*128 + lrow];
            uint32_t ssz = src >= 0 ? 16u : 0u;
            const float* ap = hsrc + (src < 0 ? 0 : src)*CH + c0 + lhalf*8;
            uint32_t ad = smA + buf2*STG_PITCH + lrow*ROW_P + lhalf*32;
            cp16(ad, ap, ssz); cp16(ad + 16, ap + 4, ssz);
            const float* bp = Wp + ((matBase + tap)*128 + lrow)*128 + c0 + lhalf*8;
            uint32_t bd = smB + buf2*STG_PITCH + lrow*ROW_P + lhalf*32;
            cp16(bd, bp, 16u); cp16(bd + 16, bp + 4, 16u);
            cp_commit();
        }
        uint32_t ao = sbuf*STG_PITCH, bo = sbuf*STG_PITCH;
#pragma unroll
        for (int ks = 0; ks < 2; ks++) {
            uint32_t kb = ks * 32;   // 8 floats = 32 bytes
            uint32_t a[2][4];
            ldsm4(a[0], Abase + ao + kb);
            ldsm4(a[1], Abase + ao + kb + 16*ROW_P);
            uint32_t b[4][4];
#pragma unroll
            for (int p = 0; p < 4; p++) ldsm4(b[p], Bbase + bo + kb + p*16*ROW_P);
#pragma unroll
            for (int mt = 0; mt < 2; mt++)
#pragma unroll
                for (int nt = 0; nt < 8; nt++)
                    mma_tf32(acc[mt][nt], a[mt], b[nt >> 1] + (nt & 1)*2);
        }
        sbuf++; if (sbuf == 3) sbuf = 0;
    }

    // ---- epilogue: register -> gmem, fused bias (+residual / +GN2 stats) ----
    float* sred = (float*)dsm;      // reuse stage smem for GN2 stat reduction
    if (!ISC2) {
        __syncthreads();
        if (tid < 64) sred[tid] = 0.f;
        __syncthreads();
    }

    // per-nt group partials: group(nt) = wn*16 + nt*2 + ((lane&3)>>1)
    float gs[8], gq[8];
#pragma unroll
    for (int nt = 0; nt < 8; nt++) { gs[nt] = 0.f; gq[nt] = 0.f; }

#pragma unroll
    for (int mt = 0; mt < 2; mt++) {
        int rl = wm*32 + mt*16 + (lane >> 2);
#pragma unroll
        for (int half = 0; half < 2; half++) {
            int row = rl + half*8;
            int orow, prow;
            if (ISC2) { orow = bx*128 + row; prow = orow >> 3; }
            else      { orow = (bx*128 + row)*8 + ko; prow = -1; }
#pragma unroll
            for (int nt = 0; nt < 8; nt++) {
                int col = wn*64 + nt*8 + (lane & 3)*2;
                float2 bb = *reinterpret_cast<const float2*>(bias + col);
                float ax = acc[mt][nt][half*2 + 0] + bb.x;
                float ay = acc[mt][nt][half*2 + 1] + bb.y;
                if (ISC2) {
                    float2 rr = *reinterpret_cast<const float2*>(feats + prow*CH + col);
                    ax += rr.x; ay += rr.y;
                } else {
                    gs[nt] += ax + ay;
                    gq[nt] += ax*ax + ay*ay;
                }
                float2 o; o.x = ax; o.y = ay;
                *reinterpret_cast<float2*>(outp + orow*CH + col) = o;
            }
        }
    }

    if (!ISC2) {
#pragma unroll
        for (int nt = 0; nt < 8; nt++) {
            int g = wn*16 + nt*2 + ((lane & 3) >> 1);
            atomicAdd(&sred[g], gs[nt]);
            atomicAdd(&sred[32 + g], gq[nt]);
        }
        __syncthreads();
        if (tid < 32) {
            atomicAdd(&g_sum2[tid], sred[tid]);
            atomicAdd(&g_sq2[tid], sred[32 + tid]);
        }
    }
}

// ================= launch =================
extern "C" void kernel_launch(void* const* d_in, const int* in_sizes, int n_in,
                              void* d_out, int out_size) {
    const float* feats  = (const float*)d_in[0];
    const float* gamma1 = (const float*)d_in[1];
    const float* beta1  = (const float*)d_in[2];
    const float* W1     = (const float*)d_in[3];
    const float* b1     = (const float*)d_in[4];
    const float* gamma2 = (const float*)d_in[5];
    const float* beta2  = (const float*)d_in[6];
    const float* W2     = (const float*)d_in[7];
    const float* b2     = (const float*)d_in[8];
    const int*   coords = (const int*)d_in[9];
    float* out = (float*)d_out;

    const int smem1 = 6*STG_PITCH + 8*128*4;    // 65536
    const int smem2 = 6*STG_PITCH + 27*128*4;   // 75264
    cudaFuncSetAttribute(k_convmma<8,false>, cudaFuncAttributeMaxDynamicSharedMemorySize, smem1);
    cudaFuncSetAttribute(k_convmma<27,true>, cudaFuncAttributeMaxDynamicSharedMemorySize, smem2);

    k_init_pg<<<128, 256>>>();
    k_scatter<<<32, 256>>>(coords);
    k_buildM1s<<<4096, 256>>>(W1);
    k_buildW2s<<<1728, 256>>>(W2);

    // GN1 + SiLU -> g_h1 (tf32-rounded)
    k_stats1<<<dim3(32, 8), 256>>>(feats, NP, 8);
    k_stats2<<<32, 32>>>(8);
    k_gnsilu<false><<<(NP*32 + 255)/256, 256>>>(feats, gamma1, beta1, 1.f/(NP*4), NP*32);

    // conv1 (parent-level, aggregated taps) -> g_out1, accumulates GN2 stats
    k_convmma<8,false><<<dim3(64, 8), 256, smem1>>>(coords, b1, nullptr, nullptr);

    // GN2 + SiLU -> g_h2 (stats already in g_sum2/g_sq2)
    k_gnsilu<true><<<(NF*32 + 255)/256, 256>>>(nullptr, gamma2, beta2, 1.f/(NF*4), NF*32);

    // conv2 (fine-level, 27 taps) + bias + residual -> out
    k_convmma<27,true><<<512, 256, smem2>>>(coords, b2, feats, out);
}

// round 8
// speedup vs baseline: 1.2499x; 1.0214x over previous
#include <cuda_runtime.h>
#include <cstdint>

#define RESP 32
#define RESF 64
#define NP   8192
#define NF   65536
#define CH   128
#define EPSV 1e-5f

// ---- scratch (device globals: allocation-free rule) ----
__device__ int   g_pg[RESP*RESP*RESP];
__device__ float g_h1[NP*CH];
__device__ float g_out1[NF*CH];
__device__ float g_h2[NF*CH];
__device__ float g_M1s[64*CH*CH];   // aggregated conv1 weights, [mat][n][k], tf32-rounded
__device__ float g_W2s[27*CH*CH];   // conv2 weights, [mat][n][k], tf32-rounded
__device__ float g_sum[32], g_sq[32];      // GN2 stats
__device__ float g_ps[32][32], g_pq[32][32];

// ================= helpers =================
__device__ __forceinline__ uint32_t smem_u32(const void* p) {
    uint32_t a;
    asm("{ .reg .u64 t; cvta.to.shared.u64 t, %1; cvt.u32.u64 %0, t; }" : "=r"(a) : "l"(p));
    return a;
}
__device__ __forceinline__ float tf32r(float x) {
    uint32_t u;
    asm("cvt.rna.tf32.f32 %0, %1;" : "=r"(u) : "f"(x));
    return __uint_as_float(u);
}
__device__ __forceinline__ void cp16(uint32_t dst, const void* src, uint32_t ssz) {
    asm volatile("cp.async.cg.shared.global [%0], [%1], 16, %2;" :: "r"(dst), "l"(src), "r"(ssz));
}
__device__ __forceinline__ void cp_commit() { asm volatile("cp.async.commit_group;"); }
#define CP_WAIT(n) asm volatile("cp.async.wait_group %0;" :: "n"(n) : "memory")

__device__ __forceinline__ void ldsm4(uint32_t* r, uint32_t addr) {
    asm volatile("ldmatrix.sync.aligned.m8n8.x4.shared.b16 {%0,%1,%2,%3}, [%4];"
        : "=r"(r[0]), "=r"(r[1]), "=r"(r[2]), "=r"(r[3]) : "r"(addr));
}
__device__ __forceinline__ void mma_tf32(float* d, const uint32_t* a, const uint32_t* b) {
    asm volatile("mma.sync.aligned.m16n8k8.row.col.f32.tf32.tf32.f32 "
        "{%0,%1,%2,%3}, {%4,%5,%6,%7}, {%8,%9}, {%0,%1,%2,%3};"
        : "+f"(d[0]), "+f"(d[1]), "+f"(d[2]), "+f"(d[3])
        : "r"(a[0]), "r"(a[1]), "r"(a[2]), "r"(a[3]), "r"(b[0]), "r"(b[1]));
}

// ================= fused grid build (single block, internal sync) =================
__global__ __launch_bounds__(1024)
void k_grid(const int* __restrict__ coords) {
    int t = threadIdx.x;
    for (int i = t; i < RESP*RESP*RESP; i += 1024) g_pg[i] = -1;
    __syncthreads();
    for (int i = t; i < NP; i += 1024)
        g_pg[(coords[i*3]*RESP + coords[i*3+1])*RESP + coords[i*3+2]] = i;
}

// ================= fused weight prep: M1 aggregate + W2 transpose, tf32 round =================
__global__ void k_prepw(const float* __restrict__ W1, const float* __restrict__ W2) {
    int idx = blockIdx.x * blockDim.x + threadIdx.x;
    if (idx < 64*CH*CH) {
        int m = idx >> 14, rest = idx & 16383;
        int n = rest >> 7, kk = rest & 127;
        int k = m >> 3, j = m & 7;
        int s[3], cnt[3];
#pragma unroll
        for (int a = 0; a < 3; a++) {
            int o  = (k >> (2 - a)) & 1;
            int eb = (j >> (2 - a)) & 1;
            cnt[a] = 1 + (o ^ eb);
            s[a]   = -1 + eb * (1 + o);
        }
        float acc = 0.f;
        for (int d0 = 0; d0 < cnt[0]; d0++)
            for (int d1 = 0; d1 < cnt[1]; d1++)
                for (int d2 = 0; d2 < cnt[2]; d2++) {
                    int k27 = ((s[0]+d0+1)*3 + (s[1]+d1+1))*3 + (s[2]+d2+1);
                    acc += W1[k27*CH*CH + kk*CH + n];
                }
        g_M1s[idx] = tf32r(acc);
    } else if (idx < 91*CH*CH) {
        int i2 = idx - 64*CH*CH;
        int m = i2 >> 14, rest = i2 & 16383;
        int n = rest >> 7, kk = rest & 127;
        g_W2s[i2] = tf32r(W2[m*CH*CH + kk*CH + n]);
    }
}

// ================= GN1: fused stats + normalize + SiLU (block per group) =================
__global__ __launch_bounds__(256)
void k_gn1(const float* __restrict__ feats,
           const float* __restrict__ gamma, const float* __restrict__ beta) {
    int g = blockIdx.x, t = threadIdx.x;
    float s = 0.f, q = 0.f;
    for (int r = t; r < NP; r += 256) {
        float4 v = *reinterpret_cast<const float4*>(feats + r*CH + g*4);
        s += (v.x + v.y) + (v.z + v.w);
        q += (v.x*v.x + v.y*v.y) + (v.z*v.z + v.w*v.w);
    }
    __shared__ float ss[256], sq[256];
    ss[t] = s; sq[t] = q;
    __syncthreads();
    for (int st = 128; st > 0; st >>= 1) {
        if (t < st) { ss[t] += ss[t+st]; sq[t] += sq[t+st]; }
        __syncthreads();
    }
    const float invcnt = 1.f / (NP * 4);
    float mean = ss[0] * invcnt;
    float var  = sq[0] * invcnt - mean * mean;
    float inv  = rsqrtf(var + EPSV);
    float4 ga = *reinterpret_cast<const float4*>(gamma + g*4);
    float4 be = *reinterpret_cast<const float4*>(beta + g*4);
    for (int r = t; r < NP; r += 256) {
        float4 v = *reinterpret_cast<const float4*>(feats + r*CH + g*4);
        float4 o; float y;
        y = (v.x - mean)*inv*ga.x + be.x; o.x = tf32r(y / (1.f + expf(-y)));
        y = (v.y - mean)*inv*ga.y + be.y; o.y = tf32r(y / (1.f + expf(-y)));
        y = (v.z - mean)*inv*ga.z + be.z; o.z = tf32r(y / (1.f + expf(-y)));
        y = (v.w - mean)*inv*ga.w + be.w; o.w = tf32r(y / (1.f + expf(-y)));
        *reinterpret_cast<float4*>(g_h1 + r*CH + g*4) = o;
    }
}

// ================= GN2 stats (two-phase over g_out1) =================
__global__ void k_stats1(int nsl) {
    int g = blockIdx.x, sl = blockIdx.y;
    int per = NF / nsl, r0 = sl * per;
    float s = 0.f, q = 0.f;
    for (int r = r0 + threadIdx.x; r < r0 + per; r += blockDim.x) {
        float4 v = *reinterpret_cast<const float4*>(g_out1 + r*CH + g*4);
        s += (v.x + v.y) + (v.z + v.w);
        q += (v.x*v.x + v.y*v.y) + (v.z*v.z + v.w*v.w);
    }
    __shared__ float ss[256], sq[256];
    ss[threadIdx.x] = s; sq[threadIdx.x] = q;
    __syncthreads();
    for (int st = 128; st > 0; st >>= 1) {
        if (threadIdx.x < st) { ss[threadIdx.x] += ss[threadIdx.x+st]; sq[threadIdx.x] += sq[threadIdx.x+st]; }
        __syncthreads();
    }
    if (threadIdx.x == 0) { g_ps[g][sl] = ss[0]; g_pq[g][sl] = sq[0]; }
}
__global__ void k_stats2(int nsl) {
    int g = blockIdx.x, t = threadIdx.x;
    float s = (t < nsl) ? g_ps[g][t] : 0.f;
    float q = (t < nsl) ? g_pq[g][t] : 0.f;
#pragma unroll
    for (int o = 16; o > 0; o >>= 1) {
        s += __shfl_xor_sync(0xffffffff, s, o);
        q += __shfl_xor_sync(0xffffffff, q, o);
    }
    if (t == 0) { g_sum[g] = s; g_sq[g] = q; }
}
__global__ void k_gnsilu2(const float* __restrict__ gamma, const float* __restrict__ beta) {
    int idx = blockIdx.x * blockDim.x + threadIdx.x;
    if (idx >= NF*32) return;
    int g = idx & 31;
    const float invcnt = 1.f / (NF * 4);
    float mean = g_sum[g] * invcnt;
    float var  = g_sq[g] * invcnt - mean * mean;
    float inv  = rsqrtf(var + EPSV);
    float4 v  = reinterpret_cast<const float4*>(g_out1)[idx];
    float4 ga = reinterpret_cast<const float4*>(gamma)[g];
    float4 be = reinterpret_cast<const float4*>(beta)[g];
    float4 o; float y;
    y = (v.x - mean)*inv*ga.x + be.x; o.x = tf32r(y / (1.f + expf(-y)));
    y = (v.y - mean)*inv*ga.y + be.y; o.y = tf32r(y / (1.f + expf(-y)));
    y = (v.z - mean)*inv*ga.z + be.z; o.z = tf32r(y / (1.f + expf(-y)));
    y = (v.w - mean)*inv*ga.w + be.w; o.w = tf32r(y / (1.f + expf(-y)));
    reinterpret_cast<float4*>(g_h2)[idx] = o;
}

// ================= tf32 mma conv kernels (R3 core, unmodified) =================
// CTA: 128 rows x 128 cols, 8 warps (4m x 2n), warp tile 32x64.
// 3-stage cp.async pipeline, BK=16, row pitch 20 floats (conflict-free ldmatrix).
#define STG_PITCH 10240          // 128 rows * 80 B
#define ROW_P 80

template<int NTAPS, bool ISC2>
__global__ __launch_bounds__(256)
void k_convmma(const int* __restrict__ coords, const float* __restrict__ bias,
               const float* __restrict__ feats, float* __restrict__ dout) {
    extern __shared__ char dsm[];
    uint32_t smA = smem_u32(dsm);              // 3 * 10240
    uint32_t smB = smA + 3*STG_PITCH;          // 3 * 10240
    int* snb = (int*)(dsm + 6*STG_PITCH);      // NTAPS*128 ints

    const float* hsrc = ISC2 ? g_h2  : g_h1;
    const float* Wp   = ISC2 ? g_W2s : g_M1s;
    float* outp       = ISC2 ? dout  : g_out1;

    int tid = threadIdx.x, lane = tid & 31, wid = tid >> 5;
    int wm = wid & 3, wn = wid >> 2;
    int bx = blockIdx.x, ko = blockIdx.y;
    const int matBase = ISC2 ? 0 : ko*8;

    // ---- neighbor precompute ----
    for (int t = tid; t < NTAPS*128; t += 256) {
        int tap = t >> 7, row = t & 127;
        int nb = -1;
        if (ISC2) {
            int grow = bx*128 + row;
            int pi = grow >> 3, k8 = grow & 7;
            int f0 = 2*coords[pi*3+0] + ((k8 >> 2) & 1) + (tap/9 - 1);
            int f1 = 2*coords[pi*3+1] + ((k8 >> 1) & 1) + ((tap/3) % 3 - 1);
            int f2 = 2*coords[pi*3+2] + (k8 & 1)        + (tap % 3 - 1);
            if ((unsigned)f0 < RESF && (unsigned)f1 < RESF && (unsigned)f2 < RESF) {
                int p = g_pg[((f0 >> 1)*RESP + (f1 >> 1))*RESP + (f2 >> 1)];
                if (p >= 0) nb = p*8 + (((f0 & 1) << 2) | ((f1 & 1) << 1) | (f2 & 1));
            }
        } else {
            int p = bx*128 + row;
            int q0 = coords[p*3+0] + ((ko >> 2) & 1) - 1 + ((tap >> 2) & 1);
            int q1 = coords[p*3+1] + ((ko >> 1) & 1) - 1 + ((tap >> 1) & 1);
            int q2 = coords[p*3+2] + (ko & 1)        - 1 + (tap & 1);
            if ((unsigned)q0 < RESP && (unsigned)q1 < RESP && (unsigned)q2 < RESP)
                nb = g_pg[(q0*RESP + q1)*RESP + q2];
        }
        snb[t] = nb;
    }
    __syncthreads();

    // per-thread loader coords: 2 cp16 for A row, 2 for B row
    const int lrow = tid >> 1, lhalf = tid & 1;

    // per-thread ldmatrix bases (stage-0 absolute; add stage offset later)
    uint32_t Abase = smA + (uint32_t)((wm*32 + ((lane>>3)&1)*8 + (lane&7))*ROW_P + ((lane>>4)&1)*16);
    uint32_t Bbase = smB + (uint32_t)((wn*64 + ((lane>>4)&1)*8 + (lane&7))*ROW_P + ((lane>>3)&1)*16);

    float acc[2][8][4];
#pragma unroll
    for (int mt = 0; mt < 2; mt++)
#pragma unroll
        for (int nt = 0; nt < 8; nt++)
#pragma unroll
            for (int c = 0; c < 4; c++) acc[mt][nt][c] = 0.f;

    const int T = NTAPS * 8;

    // prologue: stages 0,1
#pragma unroll
    for (int s = 0; s < 2; s++) {
        int tap = s >> 3, c0 = (s & 7) * 16;
        int src = snb[tap*128 + lrow];
        uint32_t ssz = src >= 0 ? 16u : 0u;
        const float* ap = hsrc + (src < 0 ? 0 : src)*CH + c0 + lhalf*8;
        uint32_t ad = smA + s*STG_PITCH + lrow*ROW_P + lhalf*32;
        cp16(ad, ap, ssz); cp16(ad + 16, ap + 4, ssz);
        const float* bp = Wp + ((matBase + tap)*128 + lrow)*128 + c0 + lhalf*8;
        uint32_t bd = smB + s*STG_PITCH + lrow*ROW_P + lhalf*32;
        cp16(bd, bp, 16u); cp16(bd + 16, bp + 4, 16u);
        cp_commit();
    }

    int sbuf = 0;
    for (int s = 0; s < T; s++) {
        if (s + 2 < T) CP_WAIT(1); else CP_WAIT(0);
        __syncthreads();
        if (s + 2 < T) {
            int s2 = s + 2;
            int tap = s2 >> 3, c0 = (s2 & 7) * 16;
            int buf2 = sbuf + 2; if (buf2 >= 3) buf2 -= 3;
            int src = snb[tap*128 + lrow];
            uint32_t ssz = src >= 0 ? 16u : 0u;
            const float* ap = hsrc + (src < 0 ? 0 : src)*CH + c0 + lhalf*8;
            uint32_t ad = smA + buf2*STG_PITCH + lrow*ROW_P + lhalf*32;
            cp16(ad, ap, ssz); cp16(ad + 16, ap + 4, ssz);
            const float* bp = Wp + ((matBase + tap)*128 + lrow)*128 + c0 + lhalf*8;
            uint32_t bd = smB + buf2*STG_PITCH + lrow*ROW_P + lhalf*32;
            cp16(bd, bp, 16u); cp16(bd + 16, bp + 4, 16u);
            cp_commit();
        }
        uint32_t ao = sbuf*STG_PITCH, bo = sbuf*STG_PITCH;
#pragma unroll
        for (int ks = 0; ks < 2; ks++) {
            uint32_t kb = ks * 32;   // 8 floats = 32 bytes
            uint32_t a[2][4];
            ldsm4(a[0], Abase + ao + kb);
            ldsm4(a[1], Abase + ao + kb + 16*ROW_P);
            uint32_t b[4][4];
#pragma unroll
            for (int p = 0; p < 4; p++) ldsm4(b[p], Bbase + bo + kb + p*16*ROW_P);
#pragma unroll
            for (int mt = 0; mt < 2; mt++)
#pragma unroll
                for (int nt = 0; nt < 8; nt++)
                    mma_tf32(acc[mt][nt], a[mt], b[nt >> 1] + (nt & 1)*2);
        }
        sbuf++; if (sbuf == 3) sbuf = 0;
    }

    // ---- epilogue: direct register -> gmem, fused bias (+residual) ----
#pragma unroll
    for (int mt = 0; mt < 2; mt++) {
        int rl = wm*32 + mt*16 + (lane >> 2);
#pragma unroll
        for (int half = 0; half < 2; half++) {
            int row = rl + half*8;
            int orow, prow;
            if (ISC2) { orow = bx*128 + row; prow = orow >> 3; }
            else      { orow = (bx*128 + row)*8 + ko; prow = -1; }
#pragma unroll
            for (int nt = 0; nt < 8; nt++) {
                int col = wn*64 + nt*8 + (lane & 3)*2;
                float2 bb = *reinterpret_cast<const float2*>(bias + col);
                float vx = acc[mt][nt][half*2 + 0] + bb.x;
                float vy = acc[mt][nt][half*2 + 1] + bb.y;
                if (ISC2) {
                    float2 rr = *reinterpret_cast<const float2*>(feats + prow*CH + col);
                    vx += rr.x; vy += rr.y;
                }
                float2 o; o.x = vx; o.y = vy;
                *reinterpret_cast<float2*>(outp + orow*CH + col) = o;
            }
        }
    }
}

// ================= launch =================
extern "C" void kernel_launch(void* const* d_in, const int* in_sizes, int n_in,
                              void* d_out, int out_size) {
    const float* feats  = (const float*)d_in[0];
    const float* gamma1 = (const float*)d_in[1];
    const float* beta1  = (const float*)d_in[2];
    const float* W1     = (const float*)d_in[3];
    const float* b1     = (const float*)d_in[4];
    const float* gamma2 = (const float*)d_in[5];
    const float* beta2  = (const float*)d_in[6];
    const float* W2     = (const float*)d_in[7];
    const float* b2     = (const float*)d_in[8];
    const int*   coords = (const int*)d_in[9];
    float* out = (float*)d_out;

    const int smem1 = 6*STG_PITCH + 8*128*4;    // 65536
    const int smem2 = 6*STG_PITCH + 27*128*4;   // 75264
    cudaFuncSetAttribute(k_convmma<8,false>, cudaFuncAttributeMaxDynamicSharedMemorySize, smem1);
    cudaFuncSetAttribute(k_convmma<27,true>, cudaFuncAttributeMaxDynamicSharedMemorySize, smem2);

    // (0) grid build (fused init+scatter)
    k_grid<<<1, 1024>>>(coords);
    // (1) weight prep (fused M1 aggregate + W2 transpose)
    k_prepw<<<(91*CH*CH + 255)/256, 256>>>(W1, W2);
    // (2) GN1 fused stats+norm+SiLU -> g_h1
    k_gn1<<<32, 256>>>(feats, gamma1, beta1);
    // (3) conv1 (parent-level, aggregated taps) -> g_out1   [ncu-profiled slot]
    k_convmma<8,false><<<dim3(64, 8), 256, smem1>>>(coords, b1, nullptr, nullptr);
    // (4,5) GN2 stats two-phase
    k_stats1<<<dim3(32, 32), 256>>>(32);
    k_stats2<<<32, 32>>>(32);
    // (6) GN2 normalize + SiLU -> g_h2
    k_gnsilu2<<<(NF*32 + 255)/256, 256>>>(gamma2, beta2);
    // (7) conv2 (fine-level, 27 taps) + bias + residual -> out
    k_convmma<27,true><<<512, 256, smem2>>>(coords, b2, feats, out);
}